// round 7
// baseline (speedup 1.0000x reference)
#include <cuda_runtime.h>
#include <cstdint>

// x is [8, 4, 1048576] fp32.
constexpr int T_IN   = 1048576;
constexpr int T_OUT  = T_IN - 12;        // 1048564
constexpr int NVEC   = T_OUT / 4;        // 262141 float4 outputs per row
constexpr int ROWS   = 8 * 4;            // 32 rows
constexpr int TPB    = 256;
constexpr int VPB    = 1024;             // output float4 vecs per tile (4096 floats)
constexpr int TILES_PER_ROW = (NVEC + VPB - 1) / VPB;   // 256
constexpr int NT     = 4;                // tiles per block (pipelined)
constexpr int BPR    = TILES_PER_ROW / NT;              // 64 blocks per row
constexpr int IN_FLOATS_FULL = VPB * 4 + 12;            // 4108 floats = 16432 B

__device__ __forceinline__ uint32_t smem_u32(const void* p) {
    uint32_t a;
    asm("{ .reg .u64 t; cvta.to.shared.u64 t, %1; cvt.u32.u64 %0, t; }"
        : "=r"(a) : "l"(p));
    return a;
}

__device__ __forceinline__ void mbar_wait(uint32_t mbar, uint32_t parity) {
    uint32_t done;
    asm volatile(
        "{\n\t"
        ".reg .pred p;\n\t"
        "mbarrier.try_wait.parity.acquire.cta.shared::cta.b64 p, [%1], %2;\n\t"
        "selp.b32 %0, 1, 0, p;\n\t"
        "}" : "=r"(done) : "r"(mbar), "r"(parity) : "memory");
    if (!done) {
        asm volatile(
            "{\n\t"
            ".reg .pred P1;\n\t"
            "WL_%=:\n\t"
            "mbarrier.try_wait.parity.acquire.cta.shared::cta.b64 P1, [%0], %1, 0x989680;\n\t"
            "@P1 bra.uni WD_%=;\n\t"
            "bra.uni WL_%=;\n\t"
            "WD_%=:\n\t"
            "}" :: "r"(mbar), "r"(parity) : "memory");
    }
}

__global__ __launch_bounds__(TPB)
void stencil13_kernel(const float* __restrict__ x,
                      const float* __restrict__ fd,
                      const float* __restrict__ gauss,
                      float* __restrict__ out) {
    __shared__ alignas(16) float s_x[2][IN_FLOATS_FULL];   // double buffer
    __shared__ float s_comp[13];
    __shared__ alignas(8) uint64_t s_mbar[2];

    const int tid = threadIdx.x;
    const int row = blockIdx.y;
    const float* xrow = x + (long)row * T_IN;
    float*       orow = out + (long)row * T_OUT;

    const int tile0 = blockIdx.x * NT;       // first tile of this block
    const uint32_t mb0 = smem_u32(&s_mbar[0]);
    const uint32_t mb1 = smem_u32(&s_mbar[1]);

    if (tid == 0) {
        asm volatile("mbarrier.init.shared.b64 [%0], 1;" :: "r"(mb0) : "memory");
        asm volatile("mbarrier.init.shared.b64 [%0], 1;" :: "r"(mb1) : "memory");
    }
    if (tid < 13) {
        float s = 0.0f;
        #pragma unroll
        for (int i = 0; i < 5; i++) {
            int j = tid - i;
            if (j >= 0 && j < 9) s += __ldg(fd + i) * __ldg(gauss + j);
        }
        s_comp[tid] = s;
    }
    __syncthreads();   // mbarriers + s_comp visible

    // Issue the first copy.
    if (tid == 0) {
        long in_base = 4096L * tile0;
        uint32_t nbytes = (uint32_t)min((long)IN_FLOATS_FULL, (long)T_IN - in_base) * 4u;
        asm volatile("mbarrier.arrive.expect_tx.shared.b64 _, [%0], %1;"
                     :: "r"(mb0), "r"(nbytes) : "memory");
        asm volatile(
            "cp.async.bulk.shared::cta.global.mbarrier::complete_tx::bytes "
            "[%0], [%1], %2, [%3];"
            :: "r"(smem_u32(s_x[0])), "l"(xrow + in_base), "r"(nbytes), "r"(mb0)
            : "memory");
    }

    float comp[13];
    #pragma unroll
    for (int k = 0; k < 13; k++) comp[k] = s_comp[k];

    #pragma unroll
    for (int i = 0; i < NT; i++) {
        // Prefetch tile i+1 into the other buffer (safe: tile i-1 consumers
        // finished at the __syncthreads() ending the previous iteration).
        if (i + 1 < NT && tid == 0) {
            const uint32_t mbn = ((i + 1) & 1) ? mb1 : mb0;
            long in_base = 4096L * (tile0 + i + 1);
            uint32_t nbytes = (uint32_t)min((long)IN_FLOATS_FULL, (long)T_IN - in_base) * 4u;
            asm volatile("mbarrier.arrive.expect_tx.shared.b64 _, [%0], %1;"
                         :: "r"(mbn), "r"(nbytes) : "memory");
            asm volatile(
                "cp.async.bulk.shared::cta.global.mbarrier::complete_tx::bytes "
                "[%0], [%1], %2, [%3];"
                :: "r"(smem_u32(s_x[(i + 1) & 1])), "l"(xrow + in_base),
                   "r"(nbytes), "r"(mbn)
                : "memory");
        }

        // Wait for tile i.
        mbar_wait((i & 1) ? mb1 : mb0, (i >> 1) & 1);

        const float* sbuf = s_x[i & 1];
        const int gvbase = (tile0 + i) * VPB;

        #pragma unroll
        for (int j = 0; j < 4; j++) {
            const int lv = tid + j * TPB;        // local output vec 0..1023
            const int gv = gvbase + lv;
            if (gv < NVEC) {
                const float4* sv = reinterpret_cast<const float4*>(sbuf + 4 * lv);
                float4 a = sv[0], b = sv[1], c = sv[2], d = sv[3];
                float xs[16] = { a.x, a.y, a.z, a.w,  b.x, b.y, b.z, b.w,
                                 c.x, c.y, c.z, c.w,  d.x, d.y, d.z, d.w };
                float o0 = 0.f, o1 = 0.f, o2 = 0.f, o3 = 0.f;
                #pragma unroll
                for (int k = 0; k < 13; k++) {
                    const float ck = comp[k];
                    o0 = fmaf(ck, xs[k + 0], o0);
                    o1 = fmaf(ck, xs[k + 1], o1);
                    o2 = fmaf(ck, xs[k + 2], o2);
                    o3 = fmaf(ck, xs[k + 3], o3);
                }
                float4 r; r.x = o0; r.y = o1; r.z = o2; r.w = o3;
                __stcs(reinterpret_cast<float4*>(orow) + gv, r);
            }
        }
        __syncthreads();   // all consumers done with buffer (i&1) before reuse
    }
}

extern "C" void kernel_launch(void* const* d_in, const int* in_sizes, int n_in,
                              void* d_out, int out_size) {
    const float* x     = (const float*)d_in[0];  // [8,4,1048576] f32
    const float* fd    = (const float*)d_in[1];  // [5]  f32
    const float* gauss = (const float*)d_in[2];  // [9]  f32
    float* out = (float*)d_out;                  // [8,4,1048564] f32

    dim3 grid(BPR, ROWS);
    stencil13_kernel<<<grid, TPB>>>(x, fd, gauss, out);
}